// round 8
// baseline (speedup 1.0000x reference)
#include <cuda_runtime.h>
#include <cuda_fp16.h>
#include <cuda_bf16.h>
#include <cstdint>

#define BB 4
#define TE 512
#define TD 256
#define HE 128
#define HD 256
#define TT 4

// ---- scratch (device globals; no allocation allowed) ----
__device__ float g_Ws[BB * TE * HE];        // enc @ W_a   [B,TE,HE]  (1 MB)
__device__ float g_Uh[BB * TD * HE];        // dec @ U_a   [B,TD,HE]  (0.5 MB)
__device__ float g_scores[BB * TD * TE];    // raw scores  [B,TD,TE]  (2 MB)

__device__ __forceinline__ __half2 tanh2_f16(__half2 x) {
    __half2 y;
    uint32_t xi = *reinterpret_cast<uint32_t*>(&x);
    uint32_t yi;
    asm("tanh.approx.f16x2 %0, %1;" : "=r"(yi) : "r"(xi));
    y = *reinterpret_cast<__half2*>(&yi);
    return y;
}

// ================= Prep kernel: Uh = dec@U  and  Ws = enc@W =================
__global__ __launch_bounds__(128) void prep_kernel(
    const float* __restrict__ dec, const float* __restrict__ U,
    const float* __restrict__ enc, const float* __restrict__ W)
{
    __shared__ float sbuf[1024];                 // 4 KB
    int tid = threadIdx.x;

    if (blockIdx.x < 256) {
        // ---- Uh: rows = B*TD, 4 per block ----
        int blk = blockIdx.x;
        int b  = blk >> 6;
        int t0 = (blk & 63) * 4;
        const float4* drow = reinterpret_cast<const float4*>(dec + ((size_t)b * TD + t0) * HD);
        float4* sb4 = reinterpret_cast<float4*>(sbuf);
#pragma unroll
        for (int i = 0; i < 2; i++) sb4[tid + 128 * i] = drow[tid + 128 * i];
        __syncthreads();

        float a0 = 0.f, a1 = 0.f, a2 = 0.f, a3 = 0.f;
#pragma unroll 4
        for (int d = 0; d < HD; d += 4) {
            float u0 = U[(d + 0) * HE + tid];
            float u1 = U[(d + 1) * HE + tid];
            float u2 = U[(d + 2) * HE + tid];
            float u3 = U[(d + 3) * HE + tid];
#pragma unroll
            for (int j = 0; j < 4; j++) {
                float uj = (j == 0) ? u0 : (j == 1) ? u1 : (j == 2) ? u2 : u3;
                a0 = fmaf(sbuf[0 * HD + d + j], uj, a0);
                a1 = fmaf(sbuf[1 * HD + d + j], uj, a1);
                a2 = fmaf(sbuf[2 * HD + d + j], uj, a2);
                a3 = fmaf(sbuf[3 * HD + d + j], uj, a3);
            }
        }
        size_t base = ((size_t)(b * TD + t0)) * HE + tid;
        g_Uh[base + 0 * HE] = a0;
        g_Uh[base + 1 * HE] = a1;
        g_Uh[base + 2 * HE] = a2;
        g_Uh[base + 3 * HE] = a3;
    } else {
        // ---- Ws: rows = B*TE, 8 per block ----
        int blk = blockIdx.x - 256;
        int b  = blk >> 6;
        int s0 = (blk & 63) * 8;
        const float4* erow = reinterpret_cast<const float4*>(enc + ((size_t)b * TE + s0) * HE);
        float4* sb4 = reinterpret_cast<float4*>(sbuf);
#pragma unroll
        for (int i = 0; i < 2; i++) sb4[tid + 128 * i] = erow[tid + 128 * i];
        __syncthreads();

        float acc[8];
#pragma unroll
        for (int r = 0; r < 8; r++) acc[r] = 0.f;
#pragma unroll 2
        for (int k = 0; k < HE; k += 4) {
            float w0 = W[(k + 0) * HE + tid];
            float w1 = W[(k + 1) * HE + tid];
            float w2 = W[(k + 2) * HE + tid];
            float w3 = W[(k + 3) * HE + tid];
#pragma unroll
            for (int r = 0; r < 8; r++) {
                float aa = acc[r];
                aa = fmaf(sbuf[r * HE + k + 0], w0, aa);
                aa = fmaf(sbuf[r * HE + k + 1], w1, aa);
                aa = fmaf(sbuf[r * HE + k + 2], w2, aa);
                aa = fmaf(sbuf[r * HE + k + 3], w3, aa);
                acc[r] = aa;
            }
        }
        size_t base = ((size_t)(b * TE + s0)) * HE + tid;
#pragma unroll
        for (int r = 0; r < 8; r++) g_Ws[base + (size_t)r * HE] = acc[r];
    }
}

// ================= Score kernel (f16x2 tanh, f32 args + accum) =================
// 1024 CTAs: blk = ((b*4 + chunk)*64 + ttile); 128 threads, thread = one s.
__global__ __launch_bounds__(128) void score_kernel(const float* __restrict__ Va)
{
    __shared__ float s_uh[TT * HE];              // 2 KB
    __shared__ float s_v[HE];                    // 0.5 KB

    int blk   = blockIdx.x;
    int ttile = blk & 63;
    int chunk = (blk >> 6) & 3;
    int b     = blk >> 8;
    int t0    = ttile * TT;
    int tid   = threadIdx.x;                     // 0..127
    int s     = chunk * 128 + tid;

    // stage Uh tile + V
#pragma unroll
    for (int i = 0; i < TT; i++)
        s_uh[i * HE + tid] = g_Uh[((size_t)(b * TD + t0 + i)) * HE + tid];
    s_v[tid] = Va[tid];
    __syncthreads();

    const float4* s_uh4 = reinterpret_cast<const float4*>(s_uh);
    const float4* s_v4  = reinterpret_cast<const float4*>(s_v);
    const float4* wrow  = reinterpret_cast<const float4*>(
        g_Ws + ((size_t)b * TE + s) * HE);

    float acc[TT];
#pragma unroll
    for (int t = 0; t < TT; t++) acc[t] = 0.f;

#pragma unroll 8
    for (int q = 0; q < HE / 4; q++) {
        float4 w = wrow[q];
        float4 v = s_v4[q];
#pragma unroll
        for (int t = 0; t < TT; t++) {
            float4 u = s_uh4[t * (HE / 4) + q];
            // f32 add -> pack f16x2 -> tanh f16x2 -> unpack to f32 -> f32 fma
            __half2 p0 = __floats2half2_rn(w.x + u.x, w.y + u.y);
            __half2 p1 = __floats2half2_rn(w.z + u.z, w.w + u.w);
            __half2 h0 = tanh2_f16(p0);
            __half2 h1 = tanh2_f16(p1);
            float a = acc[t];
            a = fmaf(__low2float(h0),  v.x, a);
            a = fmaf(__high2float(h0), v.y, a);
            a = fmaf(__low2float(h1),  v.z, a);
            a = fmaf(__high2float(h1), v.w, a);
            acc[t] = a;
        }
    }
    size_t base = ((size_t)(b * TD + t0)) * TE + s;
#pragma unroll
    for (int t = 0; t < TT; t++)
        g_scores[base + (size_t)t * TE] = acc[t];
}

// ================= Softmax + context kernel =================
// grid 256 = (b, t-tile of 4), 512 threads.
__global__ __launch_bounds__(512) void smctx_kernel(
    const float* __restrict__ enc,
    float* __restrict__ c_out,   // [B,TD,HE]
    float* __restrict__ e_out)   // [B,TD,TE]
{
    __shared__ float s_scores[TT * TE];          // 8 KB
    __shared__ float s_ctx[4][TT * HE];          // 8 KB

    int blk = blockIdx.x;
    int b  = blk / (TD / TT);
    int t0 = (blk % (TD / TT)) * TT;
    int tid  = threadIdx.x;                      // 0..511
    int warp = tid >> 5;
    int lane = tid & 31;

    // load raw scores (coalesced per t)
#pragma unroll
    for (int t = 0; t < TT; t++)
        s_scores[t * TE + tid] = g_scores[((size_t)(b * TD + t0 + t)) * TE + tid];
    __syncthreads();

    // ---- softmax per decoder step (warps 0..3) ----
    if (warp < TT) {
        int t = warp;
        float* sc = s_scores + t * TE;
        float m = -1e30f;
        for (int s = lane; s < TE; s += 32) m = fmaxf(m, sc[s]);
#pragma unroll
        for (int o = 16; o > 0; o >>= 1)
            m = fmaxf(m, __shfl_xor_sync(0xFFFFFFFFu, m, o));
        float sum = 0.f;
        for (int s = lane; s < TE; s += 32) {
            float ex = __expf(sc[s] - m);
            sc[s] = ex;
            sum += ex;
        }
#pragma unroll
        for (int o = 16; o > 0; o >>= 1)
            sum += __shfl_xor_sync(0xFFFFFFFFu, sum, o);
        float inv = 1.0f / sum;
        float* eo = e_out + ((size_t)(b * TD + t0 + t)) * TE;
        for (int s = lane; s < TE; s += 32) {
            float w = sc[s] * inv;
            sc[s] = w;
            eo[s] = w;
        }
    }
    __syncthreads();

    // ---- context: 4 groups of 128 threads split the s-range ----
    {
        int g  = tid >> 7;              // 0..3
        int ee = tid & 127;             // output feature
        const float* encb = enc + (size_t)b * TE * HE;
        float a0 = 0.f, a1 = 0.f, a2 = 0.f, a3 = 0.f;
        int sbeg = g * (TE / 4);
#pragma unroll 2
        for (int s = sbeg; s < sbeg + TE / 4; s += 4) {
            float4 w0 = *reinterpret_cast<const float4*>(&s_scores[0 * TE + s]);
            float4 w1 = *reinterpret_cast<const float4*>(&s_scores[1 * TE + s]);
            float4 w2 = *reinterpret_cast<const float4*>(&s_scores[2 * TE + s]);
            float4 w3 = *reinterpret_cast<const float4*>(&s_scores[3 * TE + s]);
            float x0 = encb[(size_t)(s + 0) * HE + ee];
            float x1 = encb[(size_t)(s + 1) * HE + ee];
            float x2 = encb[(size_t)(s + 2) * HE + ee];
            float x3 = encb[(size_t)(s + 3) * HE + ee];
            a0 = fmaf(w0.x, x0, fmaf(w0.y, x1, fmaf(w0.z, x2, fmaf(w0.w, x3, a0))));
            a1 = fmaf(w1.x, x0, fmaf(w1.y, x1, fmaf(w1.z, x2, fmaf(w1.w, x3, a1))));
            a2 = fmaf(w2.x, x0, fmaf(w2.y, x1, fmaf(w2.z, x2, fmaf(w2.w, x3, a2))));
            a3 = fmaf(w3.x, x0, fmaf(w3.y, x1, fmaf(w3.z, x2, fmaf(w3.w, x3, a3))));
        }
        s_ctx[g][0 * HE + ee] = a0;
        s_ctx[g][1 * HE + ee] = a1;
        s_ctx[g][2 * HE + ee] = a2;
        s_ctx[g][3 * HE + ee] = a3;
    }
    __syncthreads();

    // combine: 512 threads -> 512 outputs (TT*HE)
    {
        float r = s_ctx[0][tid] + s_ctx[1][tid] + s_ctx[2][tid] + s_ctx[3][tid];
        int tt = tid >> 7;
        int ee = tid & 127;
        c_out[((size_t)(b * TD + t0 + tt)) * HE + ee] = r;
    }
}

extern "C" void kernel_launch(void* const* d_in, const int* in_sizes, int n_in,
                              void* d_out, int out_size) {
    const float* enc = (const float*)d_in[0];   // [B,TE,HE]
    const float* dec = (const float*)d_in[1];   // [B,TD,HD]
    const float* Wa  = (const float*)d_in[2];   // [HE,HE]
    const float* Ua  = (const float*)d_in[3];   // [HD,HE]
    const float* Va  = (const float*)d_in[4];   // [HE,1]

    float* out   = (float*)d_out;
    float* c_out = out;                          // [B,TD,HE]
    float* e_out = out + (size_t)BB * TD * HE;   // [B,TD,TE]

    prep_kernel<<<512, 128>>>(dec, Ua, enc, Wa);
    score_kernel<<<BB * 4 * 64, 128>>>(Va);
    smctx_kernel<<<BB * (TD / TT), 512>>>(enc, c_out, e_out);
}

// round 9
// speedup vs baseline: 1.9839x; 1.9839x over previous
#include <cuda_runtime.h>
#include <cuda_fp16.h>
#include <cuda_bf16.h>
#include <cstdint>

#define BB 4
#define TE 512
#define TD 256
#define HE 128
#define HD 256
#define TT 4

// ---- scratch (device globals; no allocation allowed) ----
__device__ __half g_Wsh[BB * TE * HE];      // enc @ W_a   as half (0.5 MB)
__device__ __half g_Uhh[BB * TD * HE];      // dec @ U_a   as half (0.25 MB)
__device__ float  g_scores[BB * TD * TE];   // raw scores  [B,TD,TE]  (2 MB)

__device__ __forceinline__ __half2 tanh2_f16(__half2 x) {
    uint32_t xi = *reinterpret_cast<uint32_t*>(&x);
    uint32_t yi;
    asm("tanh.approx.f16x2 %0, %1;" : "=r"(yi) : "r"(xi));
    return *reinterpret_cast<__half2*>(&yi);
}

__device__ __forceinline__ __half2 u2h(uint32_t v) {
    return *reinterpret_cast<__half2*>(&v);
}

// ================= Prep kernel: Uh = dec@U  and  Ws = enc@W (half out) =====
__global__ __launch_bounds__(128) void prep_kernel(
    const float* __restrict__ dec, const float* __restrict__ U,
    const float* __restrict__ enc, const float* __restrict__ W)
{
    __shared__ float sbuf[1024];                 // 4 KB
    int tid = threadIdx.x;

    if (blockIdx.x < 256) {
        // ---- Uh: rows = B*TD, 4 per block ----
        int blk = blockIdx.x;
        int b  = blk >> 6;
        int t0 = (blk & 63) * 4;
        const float4* drow = reinterpret_cast<const float4*>(dec + ((size_t)b * TD + t0) * HD);
        float4* sb4 = reinterpret_cast<float4*>(sbuf);
#pragma unroll
        for (int i = 0; i < 2; i++) sb4[tid + 128 * i] = drow[tid + 128 * i];
        __syncthreads();

        float a0 = 0.f, a1 = 0.f, a2 = 0.f, a3 = 0.f;
#pragma unroll 4
        for (int d = 0; d < HD; d += 4) {
            float u0 = U[(d + 0) * HE + tid];
            float u1 = U[(d + 1) * HE + tid];
            float u2 = U[(d + 2) * HE + tid];
            float u3 = U[(d + 3) * HE + tid];
#pragma unroll
            for (int j = 0; j < 4; j++) {
                float uj = (j == 0) ? u0 : (j == 1) ? u1 : (j == 2) ? u2 : u3;
                a0 = fmaf(sbuf[0 * HD + d + j], uj, a0);
                a1 = fmaf(sbuf[1 * HD + d + j], uj, a1);
                a2 = fmaf(sbuf[2 * HD + d + j], uj, a2);
                a3 = fmaf(sbuf[3 * HD + d + j], uj, a3);
            }
        }
        size_t base = ((size_t)(b * TD + t0)) * HE + tid;
        g_Uhh[base + 0 * HE] = __float2half_rn(a0);
        g_Uhh[base + 1 * HE] = __float2half_rn(a1);
        g_Uhh[base + 2 * HE] = __float2half_rn(a2);
        g_Uhh[base + 3 * HE] = __float2half_rn(a3);
    } else {
        // ---- Ws: rows = B*TE, 8 per block ----
        int blk = blockIdx.x - 256;
        int b  = blk >> 6;
        int s0 = (blk & 63) * 8;
        const float4* erow = reinterpret_cast<const float4*>(enc + ((size_t)b * TE + s0) * HE);
        float4* sb4 = reinterpret_cast<float4*>(sbuf);
#pragma unroll
        for (int i = 0; i < 2; i++) sb4[tid + 128 * i] = erow[tid + 128 * i];
        __syncthreads();

        float acc[8];
#pragma unroll
        for (int r = 0; r < 8; r++) acc[r] = 0.f;
#pragma unroll 2
        for (int k = 0; k < HE; k += 4) {
            float w0 = W[(k + 0) * HE + tid];
            float w1 = W[(k + 1) * HE + tid];
            float w2 = W[(k + 2) * HE + tid];
            float w3 = W[(k + 3) * HE + tid];
#pragma unroll
            for (int r = 0; r < 8; r++) {
                float aa = acc[r];
                aa = fmaf(sbuf[r * HE + k + 0], w0, aa);
                aa = fmaf(sbuf[r * HE + k + 1], w1, aa);
                aa = fmaf(sbuf[r * HE + k + 2], w2, aa);
                aa = fmaf(sbuf[r * HE + k + 3], w3, aa);
                acc[r] = aa;
            }
        }
        size_t base = ((size_t)(b * TE + s0)) * HE + tid;
#pragma unroll
        for (int r = 0; r < 8; r++) g_Wsh[base + (size_t)r * HE] = __float2half_rn(acc[r]);
    }
}

// ================= Score kernel: pure-half inner loop =================
// 1024 CTAs: blk = ((b*4 + chunk)*64 + ttile); 128 threads, thread = one s.
__global__ __launch_bounds__(128) void score_kernel(const float* __restrict__ Va)
{
    __shared__ __half s_uh[TT * HE];             // 1 KB
    __shared__ __half s_v[HE];                   // 0.25 KB

    int blk   = blockIdx.x;
    int ttile = blk & 63;
    int chunk = (blk >> 6) & 3;
    int b     = blk >> 8;
    int t0    = ttile * TT;
    int tid   = threadIdx.x;                     // 0..127
    int s     = chunk * 128 + tid;

    // stage Uh tile (already half) + V (convert once)
#pragma unroll
    for (int i = 0; i < TT; i++)
        s_uh[i * HE + tid] = g_Uhh[((size_t)(b * TD + t0 + i)) * HE + tid];
    s_v[tid] = __float2half_rn(Va[tid]);
    __syncthreads();

    const uint4* s_uh4 = reinterpret_cast<const uint4*>(s_uh);   // 8 halves per uint4
    const uint4* s_v4  = reinterpret_cast<const uint4*>(s_v);
    const uint4* wrow  = reinterpret_cast<const uint4*>(
        g_Wsh + ((size_t)b * TE + s) * HE);

    __half2 zero = __float2half2_rn(0.f);
    __half2 accA[TT], accB[TT], accC[TT], accD[TT];
#pragma unroll
    for (int t = 0; t < TT; t++) { accA[t] = zero; accB[t] = zero; accC[t] = zero; accD[t] = zero; }

#pragma unroll 4
    for (int q8 = 0; q8 < HE / 8; q8++) {        // 16 iters, 8 features each
        uint4 wv = wrow[q8];
        __half2 w0 = u2h(wv.x), w1 = u2h(wv.y), w2 = u2h(wv.z), w3 = u2h(wv.w);
        uint4 vv = s_v4[q8];
        __half2 v0 = u2h(vv.x), v1 = u2h(vv.y), v2 = u2h(vv.z), v3 = u2h(vv.w);
#pragma unroll
        for (int t = 0; t < TT; t++) {
            uint4 uv = s_uh4[t * (HE / 8) + q8];
            __half2 x0 = __hadd2(w0, u2h(uv.x));
            __half2 x1 = __hadd2(w1, u2h(uv.y));
            __half2 x2 = __hadd2(w2, u2h(uv.z));
            __half2 x3 = __hadd2(w3, u2h(uv.w));
            accA[t] = __hfma2(tanh2_f16(x0), v0, accA[t]);
            accB[t] = __hfma2(tanh2_f16(x1), v1, accB[t]);
            accC[t] = __hfma2(tanh2_f16(x2), v2, accC[t]);
            accD[t] = __hfma2(tanh2_f16(x3), v3, accD[t]);
        }
    }

    size_t base = ((size_t)(b * TD + t0)) * TE + s;
#pragma unroll
    for (int t = 0; t < TT; t++) {
        // combine 4 chains in f32 for accuracy
        float2 fa = __half22float2(accA[t]);
        float2 fb = __half22float2(accB[t]);
        float2 fc = __half22float2(accC[t]);
        float2 fd = __half22float2(accD[t]);
        g_scores[base + (size_t)t * TE] =
            (fa.x + fa.y) + (fb.x + fb.y) + (fc.x + fc.y) + (fd.x + fd.y);
    }
}

// ================= Softmax + context kernel =================
// grid 256 = (b, t-tile of 4), 512 threads.
__global__ __launch_bounds__(512) void smctx_kernel(
    const float* __restrict__ enc,
    float* __restrict__ c_out,   // [B,TD,HE]
    float* __restrict__ e_out)   // [B,TD,TE]
{
    __shared__ float s_scores[TT * TE];          // 8 KB
    __shared__ float s_ctx[4][TT * HE];          // 8 KB

    int blk = blockIdx.x;
    int b  = blk / (TD / TT);
    int t0 = (blk % (TD / TT)) * TT;
    int tid  = threadIdx.x;                      // 0..511
    int warp = tid >> 5;
    int lane = tid & 31;

    // load raw scores (coalesced per t)
#pragma unroll
    for (int t = 0; t < TT; t++)
        s_scores[t * TE + tid] = g_scores[((size_t)(b * TD + t0 + t)) * TE + tid];
    __syncthreads();

    // ---- softmax per decoder step (warps 0..3) ----
    if (warp < TT) {
        int t = warp;
        float* sc = s_scores + t * TE;
        float m = -1e30f;
        for (int s = lane; s < TE; s += 32) m = fmaxf(m, sc[s]);
#pragma unroll
        for (int o = 16; o > 0; o >>= 1)
            m = fmaxf(m, __shfl_xor_sync(0xFFFFFFFFu, m, o));
        float sum = 0.f;
        for (int s = lane; s < TE; s += 32) {
            float ex = __expf(sc[s] - m);
            sc[s] = ex;
            sum += ex;
        }
#pragma unroll
        for (int o = 16; o > 0; o >>= 1)
            sum += __shfl_xor_sync(0xFFFFFFFFu, sum, o);
        float inv = 1.0f / sum;
        float* eo = e_out + ((size_t)(b * TD + t0 + t)) * TE;
        for (int s = lane; s < TE; s += 32) {
            float w = sc[s] * inv;
            sc[s] = w;
            eo[s] = w;
        }
    }
    __syncthreads();

    // ---- context: 4 groups of 128 threads split the s-range ----
    {
        int g  = tid >> 7;              // 0..3
        int ee = tid & 127;             // output feature
        const float* encb = enc + (size_t)b * TE * HE;
        float a0 = 0.f, a1 = 0.f, a2 = 0.f, a3 = 0.f;
        int sbeg = g * (TE / 4);
#pragma unroll 2
        for (int s = sbeg; s < sbeg + TE / 4; s += 4) {
            float4 w0 = *reinterpret_cast<const float4*>(&s_scores[0 * TE + s]);
            float4 w1 = *reinterpret_cast<const float4*>(&s_scores[1 * TE + s]);
            float4 w2 = *reinterpret_cast<const float4*>(&s_scores[2 * TE + s]);
            float4 w3 = *reinterpret_cast<const float4*>(&s_scores[3 * TE + s]);
            float x0 = encb[(size_t)(s + 0) * HE + ee];
            float x1 = encb[(size_t)(s + 1) * HE + ee];
            float x2 = encb[(size_t)(s + 2) * HE + ee];
            float x3 = encb[(size_t)(s + 3) * HE + ee];
            a0 = fmaf(w0.x, x0, fmaf(w0.y, x1, fmaf(w0.z, x2, fmaf(w0.w, x3, a0))));
            a1 = fmaf(w1.x, x0, fmaf(w1.y, x1, fmaf(w1.z, x2, fmaf(w1.w, x3, a1))));
            a2 = fmaf(w2.x, x0, fmaf(w2.y, x1, fmaf(w2.z, x2, fmaf(w2.w, x3, a2))));
            a3 = fmaf(w3.x, x0, fmaf(w3.y, x1, fmaf(w3.z, x2, fmaf(w3.w, x3, a3))));
        }
        s_ctx[g][0 * HE + ee] = a0;
        s_ctx[g][1 * HE + ee] = a1;
        s_ctx[g][2 * HE + ee] = a2;
        s_ctx[g][3 * HE + ee] = a3;
    }
    __syncthreads();

    // combine: 512 threads -> 512 outputs (TT*HE)
    {
        float r = s_ctx[0][tid] + s_ctx[1][tid] + s_ctx[2][tid] + s_ctx[3][tid];
        int tt = tid >> 7;
        int ee = tid & 127;
        c_out[((size_t)(b * TD + t0 + tt)) * HE + ee] = r;
    }
}

extern "C" void kernel_launch(void* const* d_in, const int* in_sizes, int n_in,
                              void* d_out, int out_size) {
    const float* enc = (const float*)d_in[0];   // [B,TE,HE]
    const float* dec = (const float*)d_in[1];   // [B,TD,HD]
    const float* Wa  = (const float*)d_in[2];   // [HE,HE]
    const float* Ua  = (const float*)d_in[3];   // [HD,HE]
    const float* Va  = (const float*)d_in[4];   // [HE,1]

    float* out   = (float*)d_out;
    float* c_out = out;                          // [B,TD,HE]
    float* e_out = out + (size_t)BB * TD * HE;   // [B,TD,TE]

    prep_kernel<<<512, 128>>>(dec, Ua, enc, Wa);
    score_kernel<<<BB * 4 * 64, 128>>>(Va);
    smctx_kernel<<<BB * (TD / TT), 512>>>(enc, c_out, e_out);
}